// round 13
// baseline (speedup 1.0000x reference)
#include <cuda_runtime.h>
#include <cstdint>

// out = var + segment_sum(value, sorted_indices)
// N=1e6 rows (D=128 f32), M=2e6 value rows, indices sorted.
//
// Kernel 1 (scatter): thread j reads idx[j-1], idx[j] (coalesced) and fills
//   g_row_start[r] = j for r in (prev, cur]; exactly N+1 writes total.
// Kernel 2 (stream): one warp per RPW=8 consecutive rows; each lane owns one
//   float4 column. Bounds fetched with ONE lane-parallel LDG (lanes 0..RPW)
//   issued before the 8 front-batched independent var loads (MLP_p1=8), then
//   shfl-broadcast; value segments contiguous; 8 streaming stores.
//   Traffic 2.05 GB -> HBM-roofline bound.

#define ROW_F4 32              // 128 floats = 32 float4 per row
#define MAX_N  1000001
#define RPW    8               // rows per warp

__device__ int g_row_start[MAX_N + 1];

__global__ void __launch_bounds__(256)
build_starts_scatter(const void* __restrict__ idx, int N, int M) {
    int j = blockIdx.x * blockDim.x + threadIdx.x;
    if (j >= M) return;

    // Dtype probe: under little-endian int64 layout, int32 slot (M&~1)-1 is
    // a high word of an index < 2^31 -> 0. Under int32 it's a late sorted
    // index (~N-1, nonzero). Uniform across the grid, L2-cached.
    const int* p32 = (const int*)idx;
    bool is64 = (__ldg(p32 + ((M & ~1) - 1)) == 0);

    int cur, prev;
    if (is64) {
        const long long* p = (const long long*)idx;
        cur  = (int)__ldg(p + j);
        prev = (j == 0) ? -1 : (int)__ldg(p + j - 1);
    } else {
        cur  = __ldg(p32 + j);
        prev = (j == 0) ? -1 : __ldg(p32 + j - 1);
    }

    for (int r = prev + 1; r <= cur; ++r) g_row_start[r] = j;
    if (j == M - 1)
        for (int r = cur + 1; r <= N; ++r) g_row_start[r] = M;
}

__global__ void __launch_bounds__(256)
seg_add_kernel(const float4* __restrict__ var,
               const float4* __restrict__ value,
               float4* __restrict__ out,
               int N) {
    int warp = (int)((blockIdx.x * (unsigned)blockDim.x + threadIdx.x) >> 5);
    int lane = threadIdx.x & 31;
    int row0 = warp * RPW;
    if (row0 >= N) return;

    // One lane-parallel bound load (lanes 0..RPW), issued FIRST so the var
    // loads below overlap its L2 latency.
    int r_ld = row0 + (lane <= RPW ? lane : RPW);
    int my_b = g_row_start[r_ld < N ? r_ld : N];

    size_t off0 = (size_t)row0 * ROW_F4 + lane;

    // Front-batch RPW independent var loads (MLP_p1 = RPW).
    float4 acc[RPW];
#pragma unroll
    for (int i = 0; i < RPW; ++i)
        if (row0 + i < N) acc[i] = __ldcs(var + off0 + (size_t)i * ROW_F4);

    // Broadcast bounds to all lanes.
    int b[RPW + 1];
#pragma unroll
    for (int i = 0; i <= RPW; ++i)
        b[i] = __shfl_sync(0xffffffffu, my_b, i);

    // Accumulate each row's contiguous value segment; loads across the RPW
    // loops are independent (all bounds already in registers).
#pragma unroll
    for (int i = 0; i < RPW; ++i) {
        size_t voff = (size_t)b[i] * ROW_F4 + lane;
        for (int m = b[i]; m < b[i + 1]; ++m, voff += ROW_F4) {
            float4 v = __ldcs(value + voff);
            acc[i].x += v.x; acc[i].y += v.y;
            acc[i].z += v.z; acc[i].w += v.w;
        }
    }

#pragma unroll
    for (int i = 0; i < RPW; ++i)
        if (row0 + i < N) __stcs(out + off0 + (size_t)i * ROW_F4, acc[i]);
}

extern "C" void kernel_launch(void* const* d_in, const int* in_sizes, int n_in,
                              void* d_out, int out_size) {
    const float* var   = (const float*)d_in[0];   // [N, 128] f32
    const float* value = (const float*)d_in[1];   // [M, 128] f32
    const void*  sidx  = d_in[2];                 // [M] int32/int64, sorted
    // d_in[3] = pos (unused)

    int N = in_sizes[0] / 128;
    int M = in_sizes[2];
    float* out = (float*)d_out;

    {   // Kernel 1: segment starts via linear scatter (M threads)
        int threads = 256;
        int blocks = (M + threads - 1) / threads;
        build_starts_scatter<<<blocks, threads>>>(sidx, N, M);
    }
    {   // Kernel 2: one warp per RPW rows
        int threads = 256;
        long long warps = ((long long)N + RPW - 1) / RPW;
        long long total_threads = warps * 32;
        int blocks = (int)((total_threads + threads - 1) / threads);
        seg_add_kernel<<<blocks, threads>>>((const float4*)var,
                                            (const float4*)value,
                                            (float4*)out, N);
    }
}

// round 15
// speedup vs baseline: 1.0644x; 1.0644x over previous
#include <cuda_runtime.h>
#include <cstdint>

// out = var + segment_sum(value, sorted_indices)
// N=1e6 rows (D=128 f32), M=2e6 value rows, indices sorted.
//
// Kernel 1 (scatter): thread j reads idx[j-1], idx[j] (coalesced) and fills
//   g_row_start[r] = j for r in (prev, cur]; exactly N+1 writes total.
// Kernel 2 (stream): one warp per RPW=4 consecutive rows (best point of the
//   RPW sweep: 1->326us, 4->303us, 8->312us). Lane-parallel bound fetch
//   (lanes 0..4, one LDG) issued FIRST, then 4 front-batched independent var
//   loads (MLP_p1=4), shfl-broadcast bounds, contiguous value segments,
//   4 streaming stores. Traffic 2.05 GB -> HBM-roofline bound.

#define ROW_F4 32              // 128 floats = 32 float4 per row
#define MAX_N  1000001
#define RPW    4               // rows per warp (sweep optimum)

__device__ int g_row_start[MAX_N + 1];

__global__ void __launch_bounds__(256)
build_starts_scatter(const void* __restrict__ idx, int N, int M) {
    int j = blockIdx.x * blockDim.x + threadIdx.x;
    if (j >= M) return;

    // Dtype probe: under little-endian int64 layout, int32 slot (M&~1)-1 is
    // a high word of an index < 2^31 -> 0. Under int32 it's a late sorted
    // index (~N-1, nonzero). Uniform across the grid, L2-cached.
    const int* p32 = (const int*)idx;
    bool is64 = (__ldg(p32 + ((M & ~1) - 1)) == 0);

    int cur, prev;
    if (is64) {
        const long long* p = (const long long*)idx;
        cur  = (int)__ldg(p + j);
        prev = (j == 0) ? -1 : (int)__ldg(p + j - 1);
    } else {
        cur  = __ldg(p32 + j);
        prev = (j == 0) ? -1 : __ldg(p32 + j - 1);
    }

    for (int r = prev + 1; r <= cur; ++r) g_row_start[r] = j;
    if (j == M - 1)
        for (int r = cur + 1; r <= N; ++r) g_row_start[r] = M;
}

__global__ void __launch_bounds__(256, 6)   // cap regs ~42 -> higher occ
seg_add_kernel(const float4* __restrict__ var,
               const float4* __restrict__ value,
               float4* __restrict__ out,
               int N) {
    int warp = (int)((blockIdx.x * (unsigned)blockDim.x + threadIdx.x) >> 5);
    int lane = threadIdx.x & 31;
    int row0 = warp * RPW;
    if (row0 >= N) return;

    // Lane-parallel bound load (lanes 0..RPW), issued FIRST so the var loads
    // below overlap its L2 latency. One LDG instead of RPW+1 uniform loads.
    int r_ld = row0 + (lane <= RPW ? lane : RPW);
    int my_b = g_row_start[r_ld < N ? r_ld : N];

    size_t off0 = (size_t)row0 * ROW_F4 + lane;

    // Front-batch RPW independent var loads (MLP_p1 = RPW).
    float4 acc[RPW];
#pragma unroll
    for (int i = 0; i < RPW; ++i)
        if (row0 + i < N) acc[i] = __ldcs(var + off0 + (size_t)i * ROW_F4);

    // Broadcast bounds to all lanes.
    int b[RPW + 1];
#pragma unroll
    for (int i = 0; i <= RPW; ++i)
        b[i] = __shfl_sync(0xffffffffu, my_b, i);

    // Accumulate each row's contiguous value segment; loads across the RPW
    // loops are independent (all bounds already in registers).
#pragma unroll
    for (int i = 0; i < RPW; ++i) {
        size_t voff = (size_t)b[i] * ROW_F4 + lane;
        for (int m = b[i]; m < b[i + 1]; ++m, voff += ROW_F4) {
            float4 v = __ldcs(value + voff);
            acc[i].x += v.x; acc[i].y += v.y;
            acc[i].z += v.z; acc[i].w += v.w;
        }
    }

#pragma unroll
    for (int i = 0; i < RPW; ++i)
        if (row0 + i < N) __stcs(out + off0 + (size_t)i * ROW_F4, acc[i]);
}

extern "C" void kernel_launch(void* const* d_in, const int* in_sizes, int n_in,
                              void* d_out, int out_size) {
    const float* var   = (const float*)d_in[0];   // [N, 128] f32
    const float* value = (const float*)d_in[1];   // [M, 128] f32
    const void*  sidx  = d_in[2];                 // [M] int32/int64, sorted
    // d_in[3] = pos (unused)

    int N = in_sizes[0] / 128;
    int M = in_sizes[2];
    float* out = (float*)d_out;

    {   // Kernel 1: segment starts via linear scatter (M threads)
        int threads = 256;
        int blocks = (M + threads - 1) / threads;
        build_starts_scatter<<<blocks, threads>>>(sidx, N, M);
    }
    {   // Kernel 2: one warp per RPW rows
        int threads = 256;
        long long warps = ((long long)N + RPW - 1) / RPW;
        long long total_threads = warps * 32;
        int blocks = (int)((total_threads + threads - 1) / threads);
        seg_add_kernel<<<blocks, threads>>>((const float4*)var,
                                            (const float4*)value,
                                            (float4*)out, N);
    }
}